// round 3
// baseline (speedup 1.0000x reference)
#include <cuda_runtime.h>

#define MEMN 64
#define BN   32
#define LN   64
#define EN   1024
#define HN   1024
#define KSPLIT 8

// ---------------- scratch (device globals; no allocation allowed) ----------
__device__ __align__(16) float g_X[MEMN * BN * EN];        // 8 MB: X[m][b][e] = sum_l inputs
__device__ __align__(16) float g_qs[BN * EN];              // sum_l questions
__device__ __align__(16) float g_upart[KSPLIT * BN * HN];  // k-split partials for u-updates
__device__ __align__(16) float g_vpart[KSPLIT * BN * EN];  // k-split partials for v = u@A^T
__device__ __align__(16) float g_y[BN * EN];               // y[b][e] = sum_m p_m X[m][b][e]
__device__ __align__(16) float g_opart[BN * HN];           // p @ TC

// ---------------- K1: reduce over L (the HBM-bound 512MB pass) -------------
__global__ void k_reduce(const float* __restrict__ inp, const float* __restrict__ q) {
    const int blk = blockIdx.x;
    const float4* src;
    float4* dst;
    if (blk < MEMN * BN) {
        src = (const float4*)(inp + (size_t)blk * LN * EN);
        dst = (float4*)(g_X + (size_t)blk * EN);
    } else {
        const int b = blk - MEMN * BN;
        src = (const float4*)(q + (size_t)b * LN * EN);
        dst = (float4*)(g_qs + (size_t)b * EN);
    }
    const int t = threadIdx.x;  // 256 threads, one float4 each => covers E=1024
    float4 a0 = make_float4(0.f, 0.f, 0.f, 0.f), a1 = a0, a2 = a0, a3 = a0;
#pragma unroll
    for (int l = 0; l < LN; l += 4) {
        float4 v0 = src[(l + 0) * (EN / 4) + t];
        float4 v1 = src[(l + 1) * (EN / 4) + t];
        float4 v2 = src[(l + 2) * (EN / 4) + t];
        float4 v3 = src[(l + 3) * (EN / 4) + t];
        a0.x += v0.x; a0.y += v0.y; a0.z += v0.z; a0.w += v0.w;
        a1.x += v1.x; a1.y += v1.y; a1.z += v1.z; a1.w += v1.w;
        a2.x += v2.x; a2.y += v2.y; a2.z += v2.z; a2.w += v2.w;
        a3.x += v3.x; a3.y += v3.y; a3.z += v3.z; a3.w += v3.w;
    }
    float4 r;
    r.x = (a0.x + a1.x) + (a2.x + a3.x);
    r.y = (a0.y + a1.y) + (a2.y + a3.y);
    r.z = (a0.z + a1.z) + (a2.z + a3.z);
    r.w = (a0.w + a1.w) + (a2.w + a3.w);
    dst[t] = r;
}

// ---------------- skinny GEMM NN: P[ks] = S[32,1024](kchunk) @ W ------------
// grid (16 n-tiles, KSPLIT), 256 threads. Output partial [KSPLIT][32][1024].
__global__ void k_gemm_nn(int use_y, const float* __restrict__ W) {
    const float* __restrict__ S = use_y ? g_y : g_qs;
    __shared__ float Ss[32][33];
    __shared__ float Ws[32][68];
    const int n0 = blockIdx.x * 64;
    const int ks = blockIdx.y;
    const int kbase = ks * (EN / KSPLIT);  // 128
    const int t = threadIdx.x;
    const int tx = t & 15, ty = t >> 4;
    float a00 = 0.f, a01 = 0.f, a02 = 0.f, a03 = 0.f;
    float a10 = 0.f, a11 = 0.f, a12 = 0.f, a13 = 0.f;
    for (int kt = 0; kt < EN / KSPLIT; kt += 32) {
        {
            int row = t >> 3, kq = (t & 7) << 2;
            float4 v = *(const float4*)(S + (size_t)row * EN + kbase + kt + kq);
            Ss[row][kq] = v.x; Ss[row][kq + 1] = v.y; Ss[row][kq + 2] = v.z; Ss[row][kq + 3] = v.w;
        }
#pragma unroll
        for (int p = 0; p < 2; ++p) {
            int row = p * 16 + ty, cq = tx << 2;
            float4 v = *(const float4*)(W + (size_t)(kbase + kt + row) * HN + n0 + cq);
            *(float4*)&Ws[row][cq] = v;
        }
        __syncthreads();
#pragma unroll
        for (int kk = 0; kk < 32; ++kk) {
            float s0 = Ss[2 * ty][kk], s1 = Ss[2 * ty + 1][kk];
            float4 w = *(const float4*)&Ws[kk][tx << 2];
            a00 += s0 * w.x; a01 += s0 * w.y; a02 += s0 * w.z; a03 += s0 * w.w;
            a10 += s1 * w.x; a11 += s1 * w.y; a12 += s1 * w.z; a13 += s1 * w.w;
        }
        __syncthreads();
    }
    float* o0 = g_upart + ((size_t)ks * BN + 2 * ty) * HN + n0 + (tx << 2);
    *(float4*)o0 = make_float4(a00, a01, a02, a03);
    *(float4*)(o0 + HN) = make_float4(a10, a11, a12, a13);
}

// ---------------- skinny GEMM NT: vpart[ks] = U[32,1024](kchunk) @ A^T ------
__global__ void k_gemm_nt(const float* __restrict__ U, const float* __restrict__ A) {
    __shared__ float Us[32][33];
    __shared__ float At[32][68];
    const int e0 = blockIdx.x * 64;
    const int ks = blockIdx.y;
    const int kbase = ks * (HN / KSPLIT);
    const int t = threadIdx.x;
    const int tx = t & 15, ty = t >> 4;
    float a00 = 0.f, a01 = 0.f, a02 = 0.f, a03 = 0.f;
    float a10 = 0.f, a11 = 0.f, a12 = 0.f, a13 = 0.f;
    for (int kt = 0; kt < HN / KSPLIT; kt += 32) {
        {
            int row = t >> 3, kq = (t & 7) << 2;
            float4 v = *(const float4*)(U + (size_t)row * HN + kbase + kt + kq);
            Us[row][kq] = v.x; Us[row][kq + 1] = v.y; Us[row][kq + 2] = v.z; Us[row][kq + 3] = v.w;
        }
#pragma unroll
        for (int p = 0; p < 2; ++p) {
            int row = p * 32 + (t >> 3), kq = (t & 7) << 2;
            float4 v = *(const float4*)(A + (size_t)(e0 + row) * HN + kbase + kt + kq);
            At[kq][row] = v.x; At[kq + 1][row] = v.y; At[kq + 2][row] = v.z; At[kq + 3][row] = v.w;
        }
        __syncthreads();
#pragma unroll
        for (int kk = 0; kk < 32; ++kk) {
            float s0 = Us[2 * ty][kk], s1 = Us[2 * ty + 1][kk];
            float4 w = *(const float4*)&At[kk][tx << 2];
            a00 += s0 * w.x; a01 += s0 * w.y; a02 += s0 * w.z; a03 += s0 * w.w;
            a10 += s1 * w.x; a11 += s1 * w.y; a12 += s1 * w.z; a13 += s1 * w.w;
        }
        __syncthreads();
    }
    float* o0 = g_vpart + ((size_t)ks * BN + 2 * ty) * EN + e0 + (tx << 2);
    *(float4*)o0 = make_float4(a00, a01, a02, a03);
    *(float4*)(o0 + EN) = make_float4(a10, a11, a12, a13);
}

// ---------------- attend: scores -> softmax -> y, p@TC ----------------------
// grid (32 batches), 256 threads. scores[b,m] = v[b].X[m,b] + u[b].TA[m]
__global__ void k_attend(const float* __restrict__ U, const float* __restrict__ TA,
                         const float* __restrict__ TC) {
    __shared__ float vs[EN];
    __shared__ float us[HN];
    __shared__ float sc[MEMN];
    const int b = blockIdx.x, t = threadIdx.x;
    {
        float4 s = make_float4(0.f, 0.f, 0.f, 0.f);
#pragma unroll
        for (int k = 0; k < KSPLIT; ++k) {
            float4 v = *(const float4*)(g_vpart + ((size_t)k * BN + b) * EN + 4 * t);
            s.x += v.x; s.y += v.y; s.z += v.z; s.w += v.w;
        }
        *(float4*)&vs[4 * t] = s;
        *(float4*)&us[4 * t] = *(const float4*)(U + (size_t)b * HN + 4 * t);
    }
    __syncthreads();
    const int warp = t >> 5, lane = t & 31;
#pragma unroll
    for (int m = warp; m < MEMN; m += 8) {
        const float* xr = g_X + ((size_t)m * BN + b) * EN;
        const float* ta = TA + (size_t)m * HN;
        float s = 0.f;
        for (int e = lane; e < EN; e += 32) s += vs[e] * xr[e] + us[e] * ta[e];
#pragma unroll
        for (int o = 16; o; o >>= 1) s += __shfl_xor_sync(0xffffffffu, s, o);
        if (lane == 0) sc[m] = s;
    }
    __syncthreads();
    if (warp == 0) {
        float s0 = sc[lane], s1 = sc[lane + 32];
        float mx = fmaxf(s0, s1);
#pragma unroll
        for (int o = 16; o; o >>= 1) mx = fmaxf(mx, __shfl_xor_sync(0xffffffffu, mx, o));
        float e0 = __expf(s0 - mx), e1 = __expf(s1 - mx);
        float sum = e0 + e1;
#pragma unroll
        for (int o = 16; o; o >>= 1) sum += __shfl_xor_sync(0xffffffffu, sum, o);
        float inv = 1.f / sum;
        sc[lane] = e0 * inv;
        sc[lane + 32] = e1 * inv;
    }
    __syncthreads();
    float4 y = make_float4(0.f, 0.f, 0.f, 0.f), op = y;
#pragma unroll 8
    for (int m = 0; m < MEMN; ++m) {
        float p = sc[m];
        float4 xv = *(const float4*)(g_X + ((size_t)m * BN + b) * EN + 4 * t);
        float4 tc = *(const float4*)(TC + (size_t)m * HN + 4 * t);
        y.x += p * xv.x; y.y += p * xv.y; y.z += p * xv.z; y.w += p * xv.w;
        op.x += p * tc.x; op.y += p * tc.y; op.z += p * tc.z; op.w += p * tc.w;
    }
    *(float4*)(g_y + (size_t)b * EN + 4 * t) = y;
    *(float4*)(g_opart + (size_t)b * HN + 4 * t) = op;
}

// ---------------- combine: u (= | +=) sum_ks upart (+ opart) ---------------
__global__ void k_combine(float* __restrict__ U, int acc) {
    const int i = blockIdx.x * blockDim.x + threadIdx.x;  // 8192 float4s
    float4 s = make_float4(0.f, 0.f, 0.f, 0.f);
#pragma unroll
    for (int k = 0; k < KSPLIT; ++k) {
        float4 v = *(const float4*)(g_upart + (size_t)k * BN * HN + 4 * i);
        s.x += v.x; s.y += v.y; s.z += v.z; s.w += v.w;
    }
    if (acc) {
        float4 u0 = *(const float4*)(U + 4 * i);
        float4 o = *(const float4*)(g_opart + 4 * i);
        s.x += u0.x + o.x; s.y += u0.y + o.y; s.z += u0.z + o.z; s.w += u0.w + o.w;
    }
    *(float4*)(U + 4 * i) = s;
}

// ---------------- launch -----------------------------------------------------
extern "C" void kernel_launch(void* const* d_in, const int* in_sizes, int n_in,
                              void* d_out, int out_size) {
    const float* inputs    = (const float*)d_in[0];  // [64,32,64,1024]
    const float* questions = (const float*)d_in[1];  // [32,64,1024]
    const float* A         = (const float*)d_in[2];  // [1024,1024]
    const float* C         = (const float*)d_in[3];  // [1024,1024]
    const float* Bmat      = (const float*)d_in[4];  // [1024,1024]
    const float* TA        = (const float*)d_in[5];  // [64,1024]
    const float* TC        = (const float*)d_in[6];  // [64,1024]
    float* u = (float*)d_out;                        // [32,1024]

    // X = sum_l inputs ; qs = sum_l questions   (HBM-bound pass)
    k_reduce<<<MEMN * BN + BN, 256>>>(inputs, questions);
    // u = qs @ Bmat
    k_gemm_nn<<<dim3(16, KSPLIT), 256>>>(0, Bmat);
    k_combine<<<32, 256>>>(u, 0);

    for (int hop = 0; hop < 3; ++hop) {
        // v = u @ A^T (k-split partials)
        k_gemm_nt<<<dim3(16, KSPLIT), 256>>>(u, A);
        // scores = v.X + u.TA -> softmax -> y = p.X, opart = p@TC
        k_attend<<<32, 256>>>(u, TA, TC);
        // upart = y @ C
        k_gemm_nn<<<dim3(16, KSPLIT), 256>>>(1, C);
        // u += sum upart + opart
        k_combine<<<32, 256>>>(u, 1);
    }
}

// round 4
// speedup vs baseline: 1.4081x; 1.4081x over previous
#include <cuda_runtime.h>

#define MEMN 64
#define BN   32
#define LN   64
#define EN   1024
#define HN   1024
#define KS   16      // k-split for skinny GEMMs
#define KC   (EN / KS)  // 64: k-chunk per block

// ---------------- scratch (device globals; no allocation allowed) ----------
__device__ __align__(16) float g_X[MEMN * BN * EN];     // 8 MB: X[m][b][e] = sum_l inputs
__device__ __align__(16) float g_qs[BN * EN];           // sum_l questions
__device__ __align__(16) float g_upart[KS * BN * HN];   // k-split partials for u-updates
__device__ __align__(16) float g_vpart[KS * BN * EN];   // k-split partials for v = u@A^T
__device__ __align__(16) float g_y[BN * EN];            // y[b][e] = sum_m p_m X[m][b][e]
__device__ __align__(16) float g_opart[BN * HN];        // p @ TC
__device__ __align__(16) float g_sc[BN * MEMN];         // raw scores

// ---------------- K1: reduce over L (the HBM-bound 512MB pass) -------------
__global__ void k_reduce(const float* __restrict__ inp, const float* __restrict__ q) {
    const int blk = blockIdx.x;
    const float4* src;
    float4* dst;
    if (blk < MEMN * BN) {
        src = (const float4*)(inp + (size_t)blk * LN * EN);
        dst = (float4*)(g_X + (size_t)blk * EN);
    } else {
        const int b = blk - MEMN * BN;
        src = (const float4*)(q + (size_t)b * LN * EN);
        dst = (float4*)(g_qs + (size_t)b * EN);
    }
    const int t = threadIdx.x;  // 256 threads, one float4 lane each (E=1024)
    float4 a[8];
#pragma unroll
    for (int j = 0; j < 8; ++j) a[j] = make_float4(0.f, 0.f, 0.f, 0.f);
#pragma unroll
    for (int l = 0; l < LN; l += 8) {
#pragma unroll
        for (int j = 0; j < 8; ++j) {
            float4 v = src[(l + j) * (EN / 4) + t];
            a[j].x += v.x; a[j].y += v.y; a[j].z += v.z; a[j].w += v.w;
        }
    }
#pragma unroll
    for (int s = 4; s; s >>= 1)
#pragma unroll
        for (int j = 0; j < s; ++j) {
            a[j].x += a[j + s].x; a[j].y += a[j + s].y;
            a[j].z += a[j + s].z; a[j].w += a[j + s].w;
        }
    dst[t] = a[0];
}

// ---------------- skinny GEMM NN: upart[ks] = S[32,kchunk] @ W[kchunk,1024] -
// grid (8 n-tiles of 128, KS), 256 threads, 4x4 micro-tile.
__global__ void k_gemm_nn(int use_y, const float* __restrict__ W) {
    const float* __restrict__ S = use_y ? g_y : g_qs;
    __shared__ float Ss[BN][68];   // [b][k], padded (272B row, 16B aligned)
    __shared__ float Ws[KC][128];  // [k][n]
    const int n0 = blockIdx.x * 128;
    const int kb = blockIdx.y * KC;
    const int t = threadIdx.x;
    // S tile: 32 x 64 floats = 512 float4, 2 per thread
#pragma unroll
    for (int j = 0; j < 2; ++j) {
        int idx = t + 256 * j;
        int b = idx >> 4, qq = idx & 15;
        *(float4*)&Ss[b][4 * qq] = *(const float4*)(S + (size_t)b * EN + kb + 4 * qq);
    }
    // W tile: 64 x 128 floats = 2048 float4, 8 per thread
#pragma unroll
    for (int j = 0; j < 8; ++j) {
        int idx = t + 256 * j;
        int k = idx >> 5, qq = idx & 31;
        *(float4*)&Ws[k][4 * qq] = *(const float4*)(W + (size_t)(kb + k) * HN + n0 + 4 * qq);
    }
    __syncthreads();
    const int tx = t & 31, ty = t >> 5;  // tx: n-group, ty: b-group
    float4 a0 = make_float4(0.f, 0.f, 0.f, 0.f), a1 = a0, a2 = a0, a3 = a0;
#pragma unroll 16
    for (int kk = 0; kk < KC; ++kk) {
        float s0 = Ss[4 * ty + 0][kk], s1 = Ss[4 * ty + 1][kk];
        float s2 = Ss[4 * ty + 2][kk], s3 = Ss[4 * ty + 3][kk];
        float4 w = *(const float4*)&Ws[kk][4 * tx];
        a0.x += s0 * w.x; a0.y += s0 * w.y; a0.z += s0 * w.z; a0.w += s0 * w.w;
        a1.x += s1 * w.x; a1.y += s1 * w.y; a1.z += s1 * w.z; a1.w += s1 * w.w;
        a2.x += s2 * w.x; a2.y += s2 * w.y; a2.z += s2 * w.z; a2.w += s2 * w.w;
        a3.x += s3 * w.x; a3.y += s3 * w.y; a3.z += s3 * w.z; a3.w += s3 * w.w;
    }
    float* o = g_upart + ((size_t)blockIdx.y * BN + 4 * ty) * HN + n0 + 4 * tx;
    *(float4*)(o + 0 * HN) = a0;
    *(float4*)(o + 1 * HN) = a1;
    *(float4*)(o + 2 * HN) = a2;
    *(float4*)(o + 3 * HN) = a3;
}

// ---------------- skinny GEMM NT: vpart[ks] = U[32,kchunk] @ A^T ------------
// A is [E,H]; need v[b,e] = sum_h U[b,h] A[e,h]. A transposed into smem with
// XOR-swizzled 16B groups for conflict-free vector reads.
__global__ void k_gemm_nt(const float* __restrict__ U, const float* __restrict__ A) {
    __shared__ float Us[BN][68];   // [b][h]
    __shared__ float As[KC][128];  // [h][e], swizzled: group g at phys g^(h&31)
    const int e0 = blockIdx.x * 128;
    const int hb = blockIdx.y * KC;
    const int t = threadIdx.x;
#pragma unroll
    for (int j = 0; j < 2; ++j) {
        int idx = t + 256 * j;
        int b = idx >> 4, qq = idx & 15;
        *(float4*)&Us[b][4 * qq] = *(const float4*)(U + (size_t)b * HN + hb + 4 * qq);
    }
    // A tile: 128 e-rows x 64 h, loaded along h (coalesced), scattered transposed
#pragma unroll
    for (int j = 0; j < 8; ++j) {
        int idx = t + 256 * j;
        int r = idx >> 4, qq = idx & 15;  // r: e-row 0..127, qq: h-group
        float4 v = *(const float4*)(A + (size_t)(e0 + r) * HN + hb + 4 * qq);
        float vv[4] = {v.x, v.y, v.z, v.w};
#pragma unroll
        for (int i = 0; i < 4; ++i) {
            int h = 4 * qq + i;
            As[h][(((r >> 2) ^ (h & 31)) << 2) + (r & 3)] = vv[i];
        }
    }
    __syncthreads();
    const int tx = t & 31, ty = t >> 5;
    float4 a0 = make_float4(0.f, 0.f, 0.f, 0.f), a1 = a0, a2 = a0, a3 = a0;
#pragma unroll 16
    for (int kk = 0; kk < KC; ++kk) {
        float s0 = Us[4 * ty + 0][kk], s1 = Us[4 * ty + 1][kk];
        float s2 = Us[4 * ty + 2][kk], s3 = Us[4 * ty + 3][kk];
        float4 w = *(const float4*)&As[kk][(tx ^ (kk & 31)) << 2];
        a0.x += s0 * w.x; a0.y += s0 * w.y; a0.z += s0 * w.z; a0.w += s0 * w.w;
        a1.x += s1 * w.x; a1.y += s1 * w.y; a1.z += s1 * w.z; a1.w += s1 * w.w;
        a2.x += s2 * w.x; a2.y += s2 * w.y; a2.z += s2 * w.z; a2.w += s2 * w.w;
        a3.x += s3 * w.x; a3.y += s3 * w.y; a3.z += s3 * w.z; a3.w += s3 * w.w;
    }
    float* o = g_vpart + ((size_t)blockIdx.y * BN + 4 * ty) * EN + e0 + 4 * tx;
    *(float4*)(o + 0 * EN) = a0;
    *(float4*)(o + 1 * EN) = a1;
    *(float4*)(o + 2 * EN) = a2;
    *(float4*)(o + 3 * EN) = a3;
}

// ---------------- K2: scores[b,m] = v[b].X[m,b] + u[b].TA[m] ----------------
// grid (32 b, 8 m-chunks), 256 threads; one warp per m.
__global__ void k_scores(const float* __restrict__ U, const float* __restrict__ TA) {
    __shared__ float vs[EN];
    __shared__ float us[HN];
    const int b = blockIdx.x, t = threadIdx.x;
    {
        float4 s = make_float4(0.f, 0.f, 0.f, 0.f);
#pragma unroll
        for (int k = 0; k < KS; ++k) {
            float4 v = *(const float4*)(g_vpart + ((size_t)k * BN + b) * EN + 4 * t);
            s.x += v.x; s.y += v.y; s.z += v.z; s.w += v.w;
        }
        *(float4*)&vs[4 * t] = s;
        *(float4*)&us[4 * t] = *(const float4*)(U + (size_t)b * HN + 4 * t);
    }
    __syncthreads();
    const int warp = t >> 5, lane = t & 31;
    const int m = blockIdx.y * 8 + warp;
    const float* xr = g_X + ((size_t)m * BN + b) * EN;
    const float* ta = TA + (size_t)m * HN;
    float s = 0.f;
#pragma unroll
    for (int it = 0; it < 8; ++it) {
        int e = it * 128 + lane * 4;
        float4 x = *(const float4*)(xr + e);
        float4 tv = *(const float4*)(ta + e);
        s += vs[e] * x.x + vs[e + 1] * x.y + vs[e + 2] * x.z + vs[e + 3] * x.w;
        s += us[e] * tv.x + us[e + 1] * tv.y + us[e + 2] * tv.z + us[e + 3] * tv.w;
    }
#pragma unroll
    for (int o = 16; o; o >>= 1) s += __shfl_xor_sync(0xffffffffu, s, o);
    if (lane == 0) g_sc[b * MEMN + m] = s;
}

// ---------------- K3: softmax + y = p.X + opart = p@TC ---------------------
// grid (32 b, 4 e-chunks of 256), 64 threads (each thread one float4).
__global__ void k_softmax_y(const float* __restrict__ TC) {
    __shared__ float p[MEMN];
    const int b = blockIdx.x, t = threadIdx.x;
    const int e0 = blockIdx.y * 256;
    if (t < MEMN) p[t] = g_sc[b * MEMN + t];
    __syncthreads();
    if (t < 32) {
        float s0 = p[t], s1 = p[t + 32];
        float mx = fmaxf(s0, s1);
#pragma unroll
        for (int o = 16; o; o >>= 1) mx = fmaxf(mx, __shfl_xor_sync(0xffffffffu, mx, o));
        float ex0 = __expf(s0 - mx), ex1 = __expf(s1 - mx);
        float sum = ex0 + ex1;
#pragma unroll
        for (int o = 16; o; o >>= 1) sum += __shfl_xor_sync(0xffffffffu, sum, o);
        float inv = 1.f / sum;
        p[t] = ex0 * inv;
        p[t + 32] = ex1 * inv;
    }
    __syncthreads();
    float4 y = make_float4(0.f, 0.f, 0.f, 0.f), op = y;
#pragma unroll 8
    for (int m = 0; m < MEMN; ++m) {
        float pm = p[m];
        float4 xv = *(const float4*)(g_X + ((size_t)m * BN + b) * EN + e0 + 4 * t);
        float4 tc = *(const float4*)(TC + (size_t)m * HN + e0 + 4 * t);
        y.x += pm * xv.x; y.y += pm * xv.y; y.z += pm * xv.z; y.w += pm * xv.w;
        op.x += pm * tc.x; op.y += pm * tc.y; op.z += pm * tc.z; op.w += pm * tc.w;
    }
    *(float4*)(g_y + (size_t)b * EN + e0 + 4 * t) = y;
    *(float4*)(g_opart + (size_t)b * HN + e0 + 4 * t) = op;
}

// ---------------- combine: u (= | +=) sum_ks upart (+ opart) ---------------
__global__ void k_combine(float* __restrict__ U, int acc) {
    const int i = blockIdx.x * blockDim.x + threadIdx.x;  // 8192 float4s
    float4 s = make_float4(0.f, 0.f, 0.f, 0.f);
#pragma unroll
    for (int k = 0; k < KS; ++k) {
        float4 v = *(const float4*)(g_upart + (size_t)k * BN * HN + 4 * i);
        s.x += v.x; s.y += v.y; s.z += v.z; s.w += v.w;
    }
    if (acc) {
        float4 u0 = *(const float4*)(U + 4 * i);
        float4 o = *(const float4*)(g_opart + 4 * i);
        s.x += u0.x + o.x; s.y += u0.y + o.y; s.z += u0.z + o.z; s.w += u0.w + o.w;
    }
    *(float4*)(U + 4 * i) = s;
}

// ---------------- launch -----------------------------------------------------
extern "C" void kernel_launch(void* const* d_in, const int* in_sizes, int n_in,
                              void* d_out, int out_size) {
    const float* inputs    = (const float*)d_in[0];  // [64,32,64,1024]
    const float* questions = (const float*)d_in[1];  // [32,64,1024]
    const float* A         = (const float*)d_in[2];  // [1024,1024]
    const float* C         = (const float*)d_in[3];  // [1024,1024]
    const float* Bmat      = (const float*)d_in[4];  // [1024,1024]
    const float* TA        = (const float*)d_in[5];  // [64,1024]
    const float* TC        = (const float*)d_in[6];  // [64,1024]
    float* u = (float*)d_out;                        // [32,1024]

    // X = sum_l inputs ; qs = sum_l questions   (HBM-bound pass)
    k_reduce<<<MEMN * BN + BN, 256>>>(inputs, questions);
    // u = qs @ Bmat
    k_gemm_nn<<<dim3(8, KS), 256>>>(0, Bmat);
    k_combine<<<32, 256>>>(u, 0);

    for (int hop = 0; hop < 3; ++hop) {
        // v = u @ A^T (k-split partials)
        k_gemm_nt<<<dim3(8, KS), 256>>>(u, A);
        // scores = v.X + u.TA
        k_scores<<<dim3(BN, 8), 256>>>(u, TA);
        // softmax -> y = p.X, opart = p@TC
        k_softmax_y<<<dim3(BN, 4), 64>>>(TC);
        // upart = y @ C
        k_gemm_nn<<<dim3(8, KS), 256>>>(1, C);
        // u += sum upart + opart
        k_combine<<<32, 256>>>(u, 1);
    }
}

// round 5
// speedup vs baseline: 1.5666x; 1.1125x over previous
#include <cuda_runtime.h>

#define MEMN 64
#define BN   32
#define LN   64
#define EN   1024
#define HN   1024
#define KS   16         // k-split for skinny GEMMs
#define KC   (EN / KS)  // 64: k-chunk per block

// ---------------- scratch (device globals; no allocation allowed) ----------
__device__ __align__(16) float g_X[MEMN * BN * EN];     // 8 MB: X[m][b][e] = sum_l inputs
__device__ __align__(16) float g_qs[BN * EN];           // sum_l questions
__device__ __align__(16) float g_At[HN * EN];           // A^T (4 MB), hop-invariant
__device__ __align__(16) float g_upart[KS * BN * HN];   // k-split partials (u-updates)
__device__ __align__(16) float g_vpart[KS * BN * EN];   // k-split partials (v = u@A^T)
__device__ __align__(16) float g_y[BN * EN];            // y[b][e] = sum_m p_m X[m][b][e]
__device__ __align__(16) float g_opart[BN * HN];        // p @ TC
__device__ __align__(16) float g_sc[BN * MEMN];         // raw scores

// ---------------- K1: reduce over L (HBM-bound 520MB pass), single wave ----
#define RED_BLOCKS 1040
__global__ void __launch_bounds__(256) k_reduce(const float* __restrict__ inp,
                                                const float* __restrict__ q) {
    const int t = threadIdx.x;
    for (int blk = blockIdx.x; blk < MEMN * BN + BN; blk += RED_BLOCKS) {
        const float4* src;
        float4* dst;
        if (blk < MEMN * BN) {
            src = (const float4*)(inp + (size_t)blk * LN * EN);
            dst = (float4*)(g_X + (size_t)blk * EN);
        } else {
            const int b = blk - MEMN * BN;
            src = (const float4*)(q + (size_t)b * LN * EN);
            dst = (float4*)(g_qs + (size_t)b * EN);
        }
        float4 a[8];
#pragma unroll
        for (int j = 0; j < 8; ++j) a[j] = make_float4(0.f, 0.f, 0.f, 0.f);
#pragma unroll
        for (int l = 0; l < LN; l += 8) {
#pragma unroll
            for (int j = 0; j < 8; ++j) {
                float4 v = src[(l + j) * (EN / 4) + t];
                a[j].x += v.x; a[j].y += v.y; a[j].z += v.z; a[j].w += v.w;
            }
        }
#pragma unroll
        for (int s = 4; s; s >>= 1)
#pragma unroll
            for (int j = 0; j < s; ++j) {
                a[j].x += a[j + s].x; a[j].y += a[j + s].y;
                a[j].z += a[j + s].z; a[j].w += a[j + s].w;
            }
        dst[t] = a[0];
    }
}

// ---------------- K1b: transpose A (once): g_At[h][e] = A[e][h] ------------
__global__ void k_transpose(const float* __restrict__ A) {
    __shared__ float tile[32][33];
    const int tx = threadIdx.x, ty = threadIdx.y;           // 32 x 8
    const int e0 = blockIdx.y * 32, h0 = blockIdx.x * 32;
#pragma unroll
    for (int j = 0; j < 32; j += 8)
        tile[ty + j][tx] = A[(size_t)(e0 + ty + j) * HN + h0 + tx];
    __syncthreads();
#pragma unroll
    for (int j = 0; j < 32; j += 8)
        g_At[(size_t)(h0 + ty + j) * EN + e0 + tx] = tile[tx][ty + j];
}

// ---------------- skinny GEMM NN: out[ks] = S[32,kc] @ W[kc,1024] ----------
// grid (16 n-tiles of 64, KS), 128 threads, 4x4 micro-tile.
__global__ void __launch_bounds__(128) k_gemm(const float* __restrict__ S,
                                              const float* __restrict__ W,
                                              float* __restrict__ out) {
    __shared__ float Ss[BN][68];   // [b][k], padded (272B rows, 16B aligned)
    __shared__ float Ws[KC][64];   // [k][n], 256B rows -> conflict-free
    const int n0 = blockIdx.x * 64;
    const int kb = blockIdx.y * KC;
    const int t = threadIdx.x;
    // S tile: 32 x 64 = 512 float4, 4 per thread
#pragma unroll
    for (int j = 0; j < 4; ++j) {
        int idx = t + 128 * j;
        int b = idx >> 4, qq = idx & 15;
        *(float4*)&Ss[b][4 * qq] = *(const float4*)(S + (size_t)b * EN + kb + 4 * qq);
    }
    // W tile: 64 x 64 = 1024 float4, 8 per thread
#pragma unroll
    for (int j = 0; j < 8; ++j) {
        int idx = t + 128 * j;
        int k = idx >> 4, qq = idx & 15;
        *(float4*)&Ws[k][4 * qq] = *(const float4*)(W + (size_t)(kb + k) * HN + n0 + 4 * qq);
    }
    __syncthreads();
    const int tx = t & 15, ty = t >> 4;  // tx: n-group(16), ty: b-group(8)
    float4 a0 = make_float4(0.f, 0.f, 0.f, 0.f), a1 = a0, a2 = a0, a3 = a0;
#pragma unroll 8
    for (int kk = 0; kk < KC; ++kk) {
        float s0 = Ss[4 * ty + 0][kk], s1 = Ss[4 * ty + 1][kk];
        float s2 = Ss[4 * ty + 2][kk], s3 = Ss[4 * ty + 3][kk];
        float4 w = *(const float4*)&Ws[kk][4 * tx];
        a0.x += s0 * w.x; a0.y += s0 * w.y; a0.z += s0 * w.z; a0.w += s0 * w.w;
        a1.x += s1 * w.x; a1.y += s1 * w.y; a1.z += s1 * w.z; a1.w += s1 * w.w;
        a2.x += s2 * w.x; a2.y += s2 * w.y; a2.z += s2 * w.z; a2.w += s2 * w.w;
        a3.x += s3 * w.x; a3.y += s3 * w.y; a3.z += s3 * w.z; a3.w += s3 * w.w;
    }
    float* o = out + ((size_t)blockIdx.y * BN + 4 * ty) * HN + n0 + 4 * tx;
    *(float4*)(o + 0 * HN) = a0;
    *(float4*)(o + 1 * HN) = a1;
    *(float4*)(o + 2 * HN) = a2;
    *(float4*)(o + 3 * HN) = a3;
}

// ---------------- K2: scores[b,m] = v[b].X[m,b] + u[b].TA[m] ----------------
// grid (32 b, 4 m-chunks of 16), 256 threads; 2 m per warp.
__global__ void __launch_bounds__(256) k_scores(const float* __restrict__ U,
                                                const float* __restrict__ TA) {
    __shared__ float vs[EN];
    __shared__ float us[HN];
    const int b = blockIdx.x, t = threadIdx.x;
    {
        float4 s = make_float4(0.f, 0.f, 0.f, 0.f);
#pragma unroll
        for (int k = 0; k < KS; ++k) {
            float4 v = *(const float4*)(g_vpart + ((size_t)k * BN + b) * EN + 4 * t);
            s.x += v.x; s.y += v.y; s.z += v.z; s.w += v.w;
        }
        *(float4*)&vs[4 * t] = s;
        *(float4*)&us[4 * t] = *(const float4*)(U + (size_t)b * HN + 4 * t);
    }
    __syncthreads();
    const int warp = t >> 5, lane = t & 31;
#pragma unroll
    for (int mm = 0; mm < 2; ++mm) {
        const int m = blockIdx.y * 16 + warp * 2 + mm;
        const float* xr = g_X + ((size_t)m * BN + b) * EN;
        const float* ta = TA + (size_t)m * HN;
        float s = 0.f;
#pragma unroll
        for (int it = 0; it < 8; ++it) {
            int e = it * 128 + lane * 4;
            float4 x = *(const float4*)(xr + e);
            float4 tv = *(const float4*)(ta + e);
            s += vs[e] * x.x + vs[e + 1] * x.y + vs[e + 2] * x.z + vs[e + 3] * x.w;
            s += us[e] * tv.x + us[e + 1] * tv.y + us[e + 2] * tv.z + us[e + 3] * tv.w;
        }
#pragma unroll
        for (int o = 16; o; o >>= 1) s += __shfl_xor_sync(0xffffffffu, s, o);
        if (lane == 0) g_sc[b * MEMN + m] = s;
    }
}

// ---------------- K3: softmax + y = p.X, opart = p@TC ----------------------
// grid (32 b, 8 e-chunks of 128), 32 threads (one warp).
__global__ void __launch_bounds__(32) k_softmax_y(const float* __restrict__ TC) {
    __shared__ float p[MEMN];
    const int b = blockIdx.x, lane = threadIdx.x;
    const int e0 = blockIdx.y * 128;
    {
        float s0 = g_sc[b * MEMN + lane], s1 = g_sc[b * MEMN + 32 + lane];
        float mx = fmaxf(s0, s1);
#pragma unroll
        for (int o = 16; o; o >>= 1) mx = fmaxf(mx, __shfl_xor_sync(0xffffffffu, mx, o));
        float ex0 = __expf(s0 - mx), ex1 = __expf(s1 - mx);
        float sum = ex0 + ex1;
#pragma unroll
        for (int o = 16; o; o >>= 1) sum += __shfl_xor_sync(0xffffffffu, sum, o);
        float inv = 1.f / sum;
        p[lane] = ex0 * inv;
        p[lane + 32] = ex1 * inv;
    }
    __syncwarp();
    float4 y = make_float4(0.f, 0.f, 0.f, 0.f), op = y;
#pragma unroll 8
    for (int m = 0; m < MEMN; ++m) {
        float pm = p[m];
        float4 xv = *(const float4*)(g_X + ((size_t)m * BN + b) * EN + e0 + 4 * lane);
        float4 tc = *(const float4*)(TC + (size_t)m * HN + e0 + 4 * lane);
        y.x += pm * xv.x; y.y += pm * xv.y; y.z += pm * xv.z; y.w += pm * xv.w;
        op.x += pm * tc.x; op.y += pm * tc.y; op.z += pm * tc.z; op.w += pm * tc.w;
    }
    *(float4*)(g_y + (size_t)b * EN + e0 + 4 * lane) = y;
    *(float4*)(g_opart + (size_t)b * HN + e0 + 4 * lane) = op;
}

// ---------------- combine: u (= | +=) sum_ks upart (+ opart) ---------------
__global__ void k_combine(float* __restrict__ U, int acc) {
    const int i = blockIdx.x * blockDim.x + threadIdx.x;  // 8192 float4s
    float4 s = make_float4(0.f, 0.f, 0.f, 0.f);
#pragma unroll
    for (int k = 0; k < KS; ++k) {
        float4 v = *(const float4*)(g_upart + (size_t)k * BN * HN + 4 * i);
        s.x += v.x; s.y += v.y; s.z += v.z; s.w += v.w;
    }
    if (acc) {
        float4 u0 = *(const float4*)(U + 4 * i);
        float4 o = *(const float4*)(g_opart + 4 * i);
        s.x += u0.x + o.x; s.y += u0.y + o.y; s.z += u0.z + o.z; s.w += u0.w + o.w;
    }
    *(float4*)(U + 4 * i) = s;
}

// ---------------- launch -----------------------------------------------------
extern "C" void kernel_launch(void* const* d_in, const int* in_sizes, int n_in,
                              void* d_out, int out_size) {
    const float* inputs    = (const float*)d_in[0];  // [64,32,64,1024]
    const float* questions = (const float*)d_in[1];  // [32,64,1024]
    const float* A         = (const float*)d_in[2];  // [1024,1024]
    const float* C         = (const float*)d_in[3];  // [1024,1024]
    const float* Bmat      = (const float*)d_in[4];  // [1024,1024]
    const float* TA        = (const float*)d_in[5];  // [64,1024]
    const float* TC        = (const float*)d_in[6];  // [64,1024]
    float* u = (float*)d_out;                        // [32,1024]

    float* g_qs_p;    cudaGetSymbolAddress((void**)&g_qs_p, g_qs);
    float* g_At_p;    cudaGetSymbolAddress((void**)&g_At_p, g_At);
    float* g_y_p;     cudaGetSymbolAddress((void**)&g_y_p, g_y);
    float* g_up_p;    cudaGetSymbolAddress((void**)&g_up_p, g_upart);
    float* g_vp_p;    cudaGetSymbolAddress((void**)&g_vp_p, g_vpart);

    // X = sum_l inputs ; qs = sum_l questions  (HBM floor, single wave)
    k_reduce<<<RED_BLOCKS, 256>>>(inputs, questions);
    // At = A^T (hop-invariant)
    k_transpose<<<dim3(32, 32), dim3(32, 8)>>>(A);
    // u = qs @ Bmat
    k_gemm<<<dim3(16, KS), 128>>>(g_qs_p, Bmat, g_up_p);
    k_combine<<<32, 256>>>(u, 0);

    for (int hop = 0; hop < 3; ++hop) {
        // v = u @ A^T  (plain NN against precomputed At)
        k_gemm<<<dim3(16, KS), 128>>>(u, g_At_p, g_vp_p);
        // scores = v.X + u.TA
        k_scores<<<dim3(BN, 4), 256>>>(u, TA);
        // softmax -> y = p.X, opart = p@TC
        k_softmax_y<<<dim3(BN, 8), 32>>>(TC);
        // upart = y @ C
        k_gemm<<<dim3(16, KS), 128>>>(g_y_p, C, g_up_p);
        // u += sum upart + opart
        k_combine<<<32, 256>>>(u, 1);
    }
}

// round 6
// speedup vs baseline: 1.6713x; 1.0668x over previous
#include <cuda_runtime.h>

#define MEMN 64
#define BN   32
#define LN   64
#define EN   1024
#define HN   1024
#define KS   8          // k-split for skinny GEMMs
#define KC   (EN / KS)  // 128: k-chunk per block

// ---------------- scratch (device globals; no allocation allowed) ----------
__device__ __align__(16) float g_X[MEMN * BN * EN];     // 8 MB: X[m][b][e] = sum_l inputs
__device__ __align__(16) float g_qs[BN * EN];           // sum_l questions
__device__ __align__(16) float g_At[HN * EN];           // A^T (4 MB), hop-invariant
__device__ __align__(16) float g_upart[KS * BN * HN];   // k-split partials (u-updates)
__device__ __align__(16) float g_vpart[KS * BN * EN];   // k-split partials (v = u@A^T)
__device__ __align__(16) float g_y[BN * EN];            // y[b][e] = sum_m p_m X[m][b][e]
__device__ __align__(16) float g_opart[BN * HN];        // p @ TC
__device__ __align__(16) float g_sc[BN * MEMN];         // raw scores

// ---------------- K1: reduce over L (HBM 520MB pass) + A-transpose ---------
// blocks [0, 2048): inputs slabs; [2048, 2080): questions; [2080, 3104): At.
__global__ void __launch_bounds__(256) k_reduce(const float* __restrict__ inp,
                                                const float* __restrict__ q,
                                                const float* __restrict__ A) {
    const int blk = blockIdx.x;
    const int t = threadIdx.x;
    if (blk >= MEMN * BN + BN) {  // transpose tile
        __shared__ float tile[32][33];
        const int blk2 = blk - (MEMN * BN + BN);
        const int h0 = (blk2 & 31) * 32, e0 = (blk2 >> 5) * 32;
        const int tx = t & 31, ty = t >> 5;  // 32 x 8
#pragma unroll
        for (int j = 0; j < 32; j += 8)
            tile[ty + j][tx] = A[(size_t)(e0 + ty + j) * HN + h0 + tx];
        __syncthreads();
#pragma unroll
        for (int j = 0; j < 32; j += 8)
            g_At[(size_t)(h0 + ty + j) * EN + e0 + tx] = tile[tx][ty + j];
        return;
    }
    const float4* src;
    float4* dst;
    if (blk < MEMN * BN) {
        src = (const float4*)(inp + (size_t)blk * LN * EN);
        dst = (float4*)(g_X + (size_t)blk * EN);
    } else {
        const int b = blk - MEMN * BN;
        src = (const float4*)(q + (size_t)b * LN * EN);
        dst = (float4*)(g_qs + (size_t)b * EN);
    }
    float4 a[8];
#pragma unroll
    for (int j = 0; j < 8; ++j) a[j] = make_float4(0.f, 0.f, 0.f, 0.f);
#pragma unroll
    for (int l = 0; l < LN; l += 8) {
#pragma unroll
        for (int j = 0; j < 8; ++j) {
            float4 v = src[(l + j) * (EN / 4) + t];
            a[j].x += v.x; a[j].y += v.y; a[j].z += v.z; a[j].w += v.w;
        }
    }
#pragma unroll
    for (int s = 4; s; s >>= 1)
#pragma unroll
        for (int j = 0; j < s; ++j) {
            a[j].x += a[j + s].x; a[j].y += a[j + s].y;
            a[j].z += a[j + s].z; a[j].w += a[j + s].w;
        }
    dst[t] = a[0];
}

// ---------------- skinny GEMM NN: out[ks] = S[32,KC] @ W[KC,1024] ----------
// grid (16 n-tiles of 64, KS=8), 128 threads, 4x4 micro-tile.
__global__ void __launch_bounds__(128) k_gemm(const float* __restrict__ S,
                                              const float* __restrict__ W,
                                              float* __restrict__ out) {
    __shared__ float Ss[BN][132];  // [b][k], padded rows (528B, 16B aligned)
    __shared__ float Ws[KC][64];   // [k][n], 256B rows -> conflict-free
    const int n0 = blockIdx.x * 64;
    const int kb = blockIdx.y * KC;
    const int t = threadIdx.x;
    // S tile: 32 x 128 = 1024 float4, 8 per thread
#pragma unroll
    for (int j = 0; j < 8; ++j) {
        int idx = t + 128 * j;
        int b = idx >> 5, qq = idx & 31;
        *(float4*)&Ss[b][4 * qq] = *(const float4*)(S + (size_t)b * EN + kb + 4 * qq);
    }
    // W tile: 128 x 64 = 2048 float4, 16 per thread
#pragma unroll
    for (int j = 0; j < 16; ++j) {
        int idx = t + 128 * j;
        int k = idx >> 4, qq = idx & 15;
        *(float4*)&Ws[k][4 * qq] = *(const float4*)(W + (size_t)(kb + k) * HN + n0 + 4 * qq);
    }
    __syncthreads();
    const int tx = t & 15, ty = t >> 4;  // tx: n-group(16), ty: b-group(8)
    float4 a0 = make_float4(0.f, 0.f, 0.f, 0.f), a1 = a0, a2 = a0, a3 = a0;
#pragma unroll 8
    for (int kk = 0; kk < KC; ++kk) {
        float s0 = Ss[4 * ty + 0][kk], s1 = Ss[4 * ty + 1][kk];
        float s2 = Ss[4 * ty + 2][kk], s3 = Ss[4 * ty + 3][kk];
        float4 w = *(const float4*)&Ws[kk][4 * tx];
        a0.x += s0 * w.x; a0.y += s0 * w.y; a0.z += s0 * w.z; a0.w += s0 * w.w;
        a1.x += s1 * w.x; a1.y += s1 * w.y; a1.z += s1 * w.z; a1.w += s1 * w.w;
        a2.x += s2 * w.x; a2.y += s2 * w.y; a2.z += s2 * w.z; a2.w += s2 * w.w;
        a3.x += s3 * w.x; a3.y += s3 * w.y; a3.z += s3 * w.z; a3.w += s3 * w.w;
    }
    float* o = out + ((size_t)blockIdx.y * BN + 4 * ty) * HN + n0 + 4 * tx;
    *(float4*)(o + 0 * HN) = a0;
    *(float4*)(o + 1 * HN) = a1;
    *(float4*)(o + 2 * HN) = a2;
    *(float4*)(o + 3 * HN) = a3;
}

// ---------------- K2: scores[b,m] = v[b].X[m,b] + u[b].TA[m] ----------------
// grid (32 b, 4 m-chunks of 16), 256 threads; 2 m per warp.
__global__ void __launch_bounds__(256) k_scores(const float* __restrict__ U,
                                                const float* __restrict__ TA) {
    __shared__ float vs[EN];
    __shared__ float us[HN];
    const int b = blockIdx.x, t = threadIdx.x;
    {
        float4 s = make_float4(0.f, 0.f, 0.f, 0.f);
#pragma unroll
        for (int k = 0; k < KS; ++k) {
            float4 v = *(const float4*)(g_vpart + ((size_t)k * BN + b) * EN + 4 * t);
            s.x += v.x; s.y += v.y; s.z += v.z; s.w += v.w;
        }
        *(float4*)&vs[4 * t] = s;
        *(float4*)&us[4 * t] = *(const float4*)(U + (size_t)b * HN + 4 * t);
    }
    __syncthreads();
    const int warp = t >> 5, lane = t & 31;
#pragma unroll
    for (int mm = 0; mm < 2; ++mm) {
        const int m = blockIdx.y * 16 + warp * 2 + mm;
        const float* xr = g_X + ((size_t)m * BN + b) * EN;
        const float* ta = TA + (size_t)m * HN;
        float s = 0.f;
#pragma unroll
        for (int it = 0; it < 8; ++it) {
            int e = it * 128 + lane * 4;
            float4 x = *(const float4*)(xr + e);
            float4 tv = *(const float4*)(ta + e);
            s += vs[e] * x.x + vs[e + 1] * x.y + vs[e + 2] * x.z + vs[e + 3] * x.w;
            s += us[e] * tv.x + us[e + 1] * tv.y + us[e + 2] * tv.z + us[e + 3] * tv.w;
        }
#pragma unroll
        for (int o = 16; o; o >>= 1) s += __shfl_xor_sync(0xffffffffu, s, o);
        if (lane == 0) g_sc[b * MEMN + m] = s;
    }
}

// ---------------- K3: softmax + y = p.X, opart = p@TC ----------------------
// grid (32 b, 8 e-chunks of 128), 32 threads (one warp).
__global__ void __launch_bounds__(32) k_softmax_y(const float* __restrict__ TC) {
    __shared__ float p[MEMN];
    const int b = blockIdx.x, lane = threadIdx.x;
    const int e0 = blockIdx.y * 128;
    {
        float s0 = g_sc[b * MEMN + lane], s1 = g_sc[b * MEMN + 32 + lane];
        float mx = fmaxf(s0, s1);
#pragma unroll
        for (int o = 16; o; o >>= 1) mx = fmaxf(mx, __shfl_xor_sync(0xffffffffu, mx, o));
        float ex0 = __expf(s0 - mx), ex1 = __expf(s1 - mx);
        float sum = ex0 + ex1;
#pragma unroll
        for (int o = 16; o; o >>= 1) sum += __shfl_xor_sync(0xffffffffu, sum, o);
        float inv = 1.f / sum;
        p[lane] = ex0 * inv;
        p[lane + 32] = ex1 * inv;
    }
    __syncwarp();
    float4 y = make_float4(0.f, 0.f, 0.f, 0.f), op = y;
#pragma unroll 8
    for (int m = 0; m < MEMN; ++m) {
        float pm = p[m];
        float4 xv = *(const float4*)(g_X + ((size_t)m * BN + b) * EN + e0 + 4 * lane);
        float4 tc = *(const float4*)(TC + (size_t)m * HN + e0 + 4 * lane);
        y.x += pm * xv.x; y.y += pm * xv.y; y.z += pm * xv.z; y.w += pm * xv.w;
        op.x += pm * tc.x; op.y += pm * tc.y; op.z += pm * tc.z; op.w += pm * tc.w;
    }
    *(float4*)(g_y + (size_t)b * EN + e0 + 4 * lane) = y;
    *(float4*)(g_opart + (size_t)b * HN + e0 + 4 * lane) = op;
}

// ---------------- combine: u (= | +=) sum_ks upart (+ opart) ---------------
// grid 128 x 64 threads: one float4 per thread, spread across all SMs.
__global__ void __launch_bounds__(64) k_combine(float* __restrict__ U, int acc) {
    const int i = blockIdx.x * 64 + threadIdx.x;  // 8192 float4s
    float4 s = make_float4(0.f, 0.f, 0.f, 0.f);
#pragma unroll
    for (int k = 0; k < KS; ++k) {
        float4 v = *(const float4*)(g_upart + (size_t)k * BN * HN + 4 * i);
        s.x += v.x; s.y += v.y; s.z += v.z; s.w += v.w;
    }
    if (acc) {
        float4 u0 = *(const float4*)(U + 4 * i);
        float4 o = *(const float4*)(g_opart + 4 * i);
        s.x += u0.x + o.x; s.y += u0.y + o.y; s.z += u0.z + o.z; s.w += u0.w + o.w;
    }
    *(float4*)(U + 4 * i) = s;
}

// ---------------- launch -----------------------------------------------------
extern "C" void kernel_launch(void* const* d_in, const int* in_sizes, int n_in,
                              void* d_out, int out_size) {
    const float* inputs    = (const float*)d_in[0];  // [64,32,64,1024]
    const float* questions = (const float*)d_in[1];  // [32,64,1024]
    const float* A         = (const float*)d_in[2];  // [1024,1024]
    const float* C         = (const float*)d_in[3];  // [1024,1024]
    const float* Bmat      = (const float*)d_in[4];  // [1024,1024]
    const float* TA        = (const float*)d_in[5];  // [64,1024]
    const float* TC        = (const float*)d_in[6];  // [64,1024]
    float* u = (float*)d_out;                        // [32,1024]

    float* g_qs_p;  cudaGetSymbolAddress((void**)&g_qs_p, g_qs);
    float* g_At_p;  cudaGetSymbolAddress((void**)&g_At_p, g_At);
    float* g_y_p;   cudaGetSymbolAddress((void**)&g_y_p, g_y);
    float* g_up_p;  cudaGetSymbolAddress((void**)&g_up_p, g_upart);
    float* g_vp_p;  cudaGetSymbolAddress((void**)&g_vp_p, g_vpart);

    // X = sum_l inputs ; qs = sum_l questions ; At = A^T  (one launch)
    k_reduce<<<MEMN * BN + BN + 1024, 256>>>(inputs, questions, A);
    // u = qs @ Bmat
    k_gemm<<<dim3(16, KS), 128>>>(g_qs_p, Bmat, g_up_p);
    k_combine<<<128, 64>>>(u, 0);

    for (int hop = 0; hop < 3; ++hop) {
        // v = u @ A^T  (plain NN against precomputed At)
        k_gemm<<<dim3(16, KS), 128>>>(u, g_At_p, g_vp_p);
        // scores = v.X + u.TA
        k_scores<<<dim3(BN, 4), 256>>>(u, TA);
        // softmax -> y = p.X, opart = p@TC
        k_softmax_y<<<dim3(BN, 8), 32>>>(TC);
        // upart = y @ C
        k_gemm<<<dim3(16, KS), 128>>>(g_y_p, C, g_up_p);
        // u += sum upart + opart
        k_combine<<<128, 64>>>(u, 1);
    }
}

// round 7
// speedup vs baseline: 1.6763x; 1.0030x over previous
#include <cuda_runtime.h>

#define MEMN 64
#define BN   32
#define LN   64
#define EN   1024
#define HN   1024
#define KS   16         // k-split for skinny GEMMs
#define KC   (EN / KS)  // 64: k-chunk per block
#define NV   1088       // width of [A^T | TA^T] and of vpart rows

// ---------------- scratch (device globals; no allocation allowed) ----------
__device__ __align__(16) float g_X[MEMN * BN * EN];     // 8 MB: X[m][b][e] = sum_l inputs
__device__ __align__(16) float g_qs[BN * EN];           // sum_l questions
__device__ __align__(16) float g_AtX[HN * NV];          // [A^T | TA^T], hop-invariant
__device__ __align__(16) float g_upart[KS * BN * HN];   // k-split partials (u-updates)
__device__ __align__(16) float g_vpart[KS * BN * NV];   // k-split partials (v | uTA)
__device__ __align__(16) float g_y[BN * EN];            // y[b][e] = sum_m p_m X[m][b][e]
__device__ __align__(16) float g_opart[BN * HN];        // p @ TC

// ---------------- K1: reduce over L (HBM 520MB) + build [A^T | TA^T] -------
// blocks [0,2048): inputs; [2048,2080): questions; [2080,3104): At; [3104,3168): TA^T.
__global__ void __launch_bounds__(256) k_reduce(const float* __restrict__ inp,
                                                const float* __restrict__ q,
                                                const float* __restrict__ A,
                                                const float* __restrict__ TA) {
    const int blk = blockIdx.x;
    const int t = threadIdx.x;
    if (blk >= MEMN * BN + BN) {  // transpose tiles
        __shared__ float tile[32][33];
        const int tx = t & 31, ty = t >> 5;  // 32 x 8
        int blk2 = blk - (MEMN * BN + BN);
        if (blk2 < 1024) {  // At: g_AtX[h][e] = A[e][h]
            const int h0 = (blk2 & 31) * 32, e0 = (blk2 >> 5) * 32;
#pragma unroll
            for (int j = 0; j < 32; j += 8)
                tile[ty + j][tx] = A[(size_t)(e0 + ty + j) * HN + h0 + tx];
            __syncthreads();
#pragma unroll
            for (int j = 0; j < 32; j += 8)
                g_AtX[(size_t)(h0 + ty + j) * NV + e0 + tx] = tile[tx][ty + j];
        } else {            // TA^T: g_AtX[h][1024+m] = TA[m][h]
            blk2 -= 1024;   // 0..63
            const int h0 = (blk2 >> 1) * 32, m0 = (blk2 & 1) * 32;
#pragma unroll
            for (int j = 0; j < 32; j += 8)
                tile[ty + j][tx] = TA[(size_t)(m0 + ty + j) * HN + h0 + tx];
            __syncthreads();
#pragma unroll
            for (int j = 0; j < 32; j += 8)
                g_AtX[(size_t)(h0 + ty + j) * NV + 1024 + m0 + tx] = tile[tx][ty + j];
        }
        return;
    }
    const float4* src;
    float4* dst;
    if (blk < MEMN * BN) {
        src = (const float4*)(inp + (size_t)blk * LN * EN);
        dst = (float4*)(g_X + (size_t)blk * EN);
    } else {
        const int b = blk - MEMN * BN;
        src = (const float4*)(q + (size_t)b * LN * EN);
        dst = (float4*)(g_qs + (size_t)b * EN);
    }
    float4 a[8];
#pragma unroll
    for (int j = 0; j < 8; ++j) a[j] = make_float4(0.f, 0.f, 0.f, 0.f);
#pragma unroll
    for (int l = 0; l < LN; l += 8) {
#pragma unroll
        for (int j = 0; j < 8; ++j) {
            float4 v = src[(l + j) * (EN / 4) + t];
            a[j].x += v.x; a[j].y += v.y; a[j].z += v.z; a[j].w += v.w;
        }
    }
#pragma unroll
    for (int s = 4; s; s >>= 1)
#pragma unroll
        for (int j = 0; j < s; ++j) {
            a[j].x += a[j + s].x; a[j].y += a[j + s].y;
            a[j].z += a[j + s].z; a[j].w += a[j + s].w;
        }
    dst[t] = a[0];
}

// ---------------- skinny GEMM NN: out[ks] = S[32,KC] @ W[KC,nw] ------------
// grid (nw/64 n-tiles, KS), 128 threads, 4x4 micro-tile. nw = row width of W & out.
__global__ void __launch_bounds__(128) k_gemm(const float* __restrict__ S,
                                              const float* __restrict__ W,
                                              float* __restrict__ out, int nw) {
    __shared__ float Ss[BN][68];   // [b][k], padded
    __shared__ float Ws[KC][64];   // [k][n]
    const int n0 = blockIdx.x * 64;
    const int kb = blockIdx.y * KC;
    const int t = threadIdx.x;
#pragma unroll
    for (int j = 0; j < 4; ++j) {  // S: 32x64 = 512 f4
        int idx = t + 128 * j;
        int b = idx >> 4, qq = idx & 15;
        *(float4*)&Ss[b][4 * qq] = *(const float4*)(S + (size_t)b * EN + kb + 4 * qq);
    }
#pragma unroll
    for (int j = 0; j < 8; ++j) {  // W: 64x64 = 1024 f4
        int idx = t + 128 * j;
        int k = idx >> 4, qq = idx & 15;
        *(float4*)&Ws[k][4 * qq] = *(const float4*)(W + (size_t)(kb + k) * nw + n0 + 4 * qq);
    }
    __syncthreads();
    const int tx = t & 15, ty = t >> 4;
    float4 a0 = make_float4(0.f, 0.f, 0.f, 0.f), a1 = a0, a2 = a0, a3 = a0;
#pragma unroll 16
    for (int kk = 0; kk < KC; ++kk) {
        float s0 = Ss[4 * ty + 0][kk], s1 = Ss[4 * ty + 1][kk];
        float s2 = Ss[4 * ty + 2][kk], s3 = Ss[4 * ty + 3][kk];
        float4 w = *(const float4*)&Ws[kk][4 * tx];
        a0.x += s0 * w.x; a0.y += s0 * w.y; a0.z += s0 * w.z; a0.w += s0 * w.w;
        a1.x += s1 * w.x; a1.y += s1 * w.y; a1.z += s1 * w.z; a1.w += s1 * w.w;
        a2.x += s2 * w.x; a2.y += s2 * w.y; a2.z += s2 * w.z; a2.w += s2 * w.w;
        a3.x += s3 * w.x; a3.y += s3 * w.y; a3.z += s3 * w.z; a3.w += s3 * w.w;
    }
    float* o = out + ((size_t)blockIdx.y * BN + 4 * ty) * nw + n0 + 4 * tx;
    *(float4*)(o + 0 * nw) = a0;
    *(float4*)(o + 1 * nw) = a1;
    *(float4*)(o + 2 * nw) = a2;
    *(float4*)(o + 3 * nw) = a3;
}

// ---------------- K2: fused attend: scores -> softmax -> y, opart ----------
// grid (32 b, 4 e-chunks of 256), 256 threads. scores recomputed per chunk.
__global__ void __launch_bounds__(256) k_attend(const float* __restrict__ TC) {
    __shared__ float vs[EN];
    __shared__ float uta[MEMN];
    __shared__ float sc[MEMN];
    __shared__ float p[MEMN];
    const int b = blockIdx.x, t = threadIdx.x;
    // Phase 1: vs = sum_ks vpart[ks][b][0:1024]; uta[m] = sum_ks vpart[ks][b][1024+m]
    {
        float4 s = make_float4(0.f, 0.f, 0.f, 0.f);
#pragma unroll
        for (int k = 0; k < KS; ++k) {
            float4 v = *(const float4*)(g_vpart + ((size_t)k * BN + b) * NV + 4 * t);
            s.x += v.x; s.y += v.y; s.z += v.z; s.w += v.w;
        }
        *(float4*)&vs[4 * t] = s;
        if (t < MEMN) {
            float su = 0.f;
#pragma unroll
            for (int k = 0; k < KS; ++k)
                su += g_vpart[((size_t)k * BN + b) * NV + 1024 + t];
            uta[t] = su;
        }
    }
    __syncthreads();
    // Phase 2: scores. 8 warps x 8 m each.
    const int warp = t >> 5, lane = t & 31;
#pragma unroll
    for (int i = 0; i < 8; ++i) {
        const int m = i * 8 + warp;
        const float* xr = g_X + ((size_t)m * BN + b) * EN;
        float s = 0.f;
#pragma unroll
        for (int it = 0; it < 8; ++it) {
            int e = it * 128 + lane * 4;
            float4 x = *(const float4*)(xr + e);
            s += vs[e] * x.x + vs[e + 1] * x.y + vs[e + 2] * x.z + vs[e + 3] * x.w;
        }
#pragma unroll
        for (int o = 16; o; o >>= 1) s += __shfl_xor_sync(0xffffffffu, s, o);
        if (lane == 0) sc[m] = s + uta[m];
    }
    __syncthreads();
    // Phase 3: softmax (warp 0)
    if (warp == 0) {
        float s0 = sc[lane], s1 = sc[lane + 32];
        float mx = fmaxf(s0, s1);
#pragma unroll
        for (int o = 16; o; o >>= 1) mx = fmaxf(mx, __shfl_xor_sync(0xffffffffu, mx, o));
        float e0 = __expf(s0 - mx), e1 = __expf(s1 - mx);
        float sum = e0 + e1;
#pragma unroll
        for (int o = 16; o; o >>= 1) sum += __shfl_xor_sync(0xffffffffu, sum, o);
        float inv = 1.f / sum;
        p[lane] = e0 * inv;
        p[lane + 32] = e1 * inv;
    }
    __syncthreads();
    // Phase 4: this chunk's y and opart (threads 0..127: 64 f4 y + 64 f4 op)
    const int e0 = blockIdx.y * 256;
    if (t < 128) {
        const int isop = t >> 6, sl = t & 63;
        const float* base = isop ? (TC + (size_t)0 * HN + e0 + 4 * sl)
                                 : (g_X + (size_t)b * EN + e0 + 4 * sl);
        const size_t stride = isop ? (size_t)HN : (size_t)BN * EN;
        float4 acc = make_float4(0.f, 0.f, 0.f, 0.f);
#pragma unroll 8
        for (int m = 0; m < MEMN; ++m) {
            float pm = p[m];
            float4 v = *(const float4*)(base + m * stride);
            acc.x += pm * v.x; acc.y += pm * v.y; acc.z += pm * v.z; acc.w += pm * v.w;
        }
        float* dst = isop ? (g_opart + (size_t)b * HN + e0 + 4 * sl)
                          : (g_y + (size_t)b * EN + e0 + 4 * sl);
        *(float4*)dst = acc;
    }
}

// ---------------- combine: u (= | +=) sum_ks upart (+ opart) ---------------
__global__ void __launch_bounds__(64) k_combine(float* __restrict__ U, int acc) {
    const int i = blockIdx.x * 64 + threadIdx.x;  // 8192 float4s
    float4 s = make_float4(0.f, 0.f, 0.f, 0.f);
#pragma unroll
    for (int k = 0; k < KS; ++k) {
        float4 v = *(const float4*)(g_upart + (size_t)k * BN * HN + 4 * i);
        s.x += v.x; s.y += v.y; s.z += v.z; s.w += v.w;
    }
    if (acc) {
        float4 u0 = *(const float4*)(U + 4 * i);
        float4 o = *(const float4*)(g_opart + 4 * i);
        s.x += u0.x + o.x; s.y += u0.y + o.y; s.z += u0.z + o.z; s.w += u0.w + o.w;
    }
    *(float4*)(U + 4 * i) = s;
}

// ---------------- launch -----------------------------------------------------
extern "C" void kernel_launch(void* const* d_in, const int* in_sizes, int n_in,
                              void* d_out, int out_size) {
    const float* inputs    = (const float*)d_in[0];  // [64,32,64,1024]
    const float* questions = (const float*)d_in[1];  // [32,64,1024]
    const float* A         = (const float*)d_in[2];  // [1024,1024]
    const float* C         = (const float*)d_in[3];  // [1024,1024]
    const float* Bmat      = (const float*)d_in[4];  // [1024,1024]
    const float* TA        = (const float*)d_in[5];  // [64,1024]
    const float* TC        = (const float*)d_in[6];  // [64,1024]
    float* u = (float*)d_out;                        // [32,1024]

    float* g_qs_p;   cudaGetSymbolAddress((void**)&g_qs_p, g_qs);
    float* g_AtX_p;  cudaGetSymbolAddress((void**)&g_AtX_p, g_AtX);
    float* g_y_p;    cudaGetSymbolAddress((void**)&g_y_p, g_y);
    float* g_up_p;   cudaGetSymbolAddress((void**)&g_up_p, g_upart);
    float* g_vp_p;   cudaGetSymbolAddress((void**)&g_vp_p, g_vpart);

    // X = sum_l inputs ; qs = sum_l questions ; AtX = [A^T | TA^T]
    k_reduce<<<MEMN * BN + BN + 1024 + 64, 256>>>(inputs, questions, A, TA);
    // u = qs @ Bmat
    k_gemm<<<dim3(16, KS), 128>>>(g_qs_p, Bmat, g_up_p, HN);
    k_combine<<<128, 64>>>(u, 0);

    for (int hop = 0; hop < 3; ++hop) {
        // [v | uTA] = u @ [A^T | TA^T]
        k_gemm<<<dim3(17, KS), 128>>>(u, g_AtX_p, g_vp_p, NV);
        // scores -> softmax -> y = p.X, opart = p@TC (fused)
        k_attend<<<dim3(BN, 4), 256>>>(TC);
        // upart = y @ C
        k_gemm<<<dim3(16, KS), 128>>>(g_y_p, C, g_up_p, HN);
        // u += sum upart + opart
        k_combine<<<128, 64>>>(u, 1);
    }
}